// round 5
// baseline (speedup 1.0000x reference)
#include <cuda_runtime.h>
#include <cuda_bf16.h>
#include <math.h>

#define BB 2
#define CC 256
#define H2 128
#define W2 128
#define FWS 8
#define NWIN 512      // BB * 16 * 16
#define NPOS 64
#define NHEADS 8
#define HD 32
#define ATT_SCALE 0.17677669529663687f  // 32^-0.5

// Scratch in window layout: [win][ch][p], p = iy*8+ix
__device__ float g_llw  [NWIN * CC * NPOS];
__device__ float g_lhw  [NWIN * CC * NPOS];
__device__ float g_hlw  [NWIN * CC * NPOS];
__device__ float g_hhw  [NWIN * CC * NPOS];
__device__ float g_llout[NWIN * CC * NPOS];

// ---------------------------------------------------------------------------
// Kernel A: forward wavelet (depthwise 2x2 stride-2), write window layout
// ---------------------------------------------------------------------------
__global__ void wt_kernel(const float* __restrict__ x, const float* __restrict__ wf) {
    int idx = blockIdx.x * blockDim.x + threadIdx.x;
    if (idx >= BB * CC * H2 * W2) return;
    int xx = idx & 127;
    int y  = (idx >> 7) & 127;
    int ch = (idx >> 14) & 255;
    int b  = idx >> 22;

    const float* px = x + (((size_t)(b * CC + ch) * 256 + 2 * y) * 256 + 2 * xx);
    float r00 = px[0], r01 = px[1], r10 = px[256], r11 = px[257];

    int win = b * 256 + (y >> 3) * 16 + (xx >> 3);
    int off = (win * CC + ch) * NPOS + (y & 7) * 8 + (xx & 7);
    const float* w = wf + ch * 16;  // wt_filter[(4ch+j)][0][ky][kx], 16 floats per ch

    g_llw[off] = w[0]  * r00 + w[1]  * r01 + w[2]  * r10 + w[3]  * r11;
    g_lhw[off] = w[4]  * r00 + w[5]  * r01 + w[6]  * r10 + w[7]  * r11;
    g_hlw[off] = w[8]  * r00 + w[9]  * r01 + w[10] * r10 + w[11] * r11;
    g_hhw[off] = w[12] * r00 + w[13] * r01 + w[14] * r10 + w[15] * r11;
}

// ---------------------------------------------------------------------------
// Kernel B: per-window cascaded head attention + relu + proj
// one CTA per window, 256 threads
// ---------------------------------------------------------------------------
__global__ void attn_kernel(const float* __restrict__ dw_w,
                            const float* __restrict__ dw_b,
                            const float* __restrict__ proj_w,
                            const float* __restrict__ proj_b,
                            const float* __restrict__ ab,
                            const int*   __restrict__ bias_idx) {
    extern __shared__ float sm[];
    float* s_ab   = sm;               // 512   (8 heads x 64 offsets)
    float* s_w    = s_ab + 512;       // 800   (32 ch x 25 taps)
    float* s_lh   = s_w + 800;        // 2048
    float* s_k    = s_lh + 2048;      // 2048
    float* s_v    = s_k + 2048;       // 2048
    float* s_q    = s_v + 2048;       // 2048  layout [d][p]
    float* s_attn = s_q + 2048;       // 64*65 (padded rows, conflict-free)
    float* s_out  = s_attn + 64 * 65; // 256*64 relu'd head outputs

    int win = blockIdx.x;
    int tid = threadIdx.x;

    for (int i = tid; i < 512; i += 256) s_ab[i] = ab[i];
    {   // head-0 v = llw[:, 0:32]
        int base = (win * CC) * NPOS;
        for (int i = tid; i < HD * NPOS; i += 256) s_v[i] = g_llw[base + i];
    }

    for (int h = 0; h < NHEADS; ++h) {
        int base = (win * CC + h * HD) * NPOS;
        for (int i = tid; i < HD * NPOS; i += 256) {
            s_lh[i] = g_lhw[base + i];
            s_k[i]  = g_hlw[base + i];
        }
        for (int i = tid; i < HD * 25; i += 256) s_w[i] = dw_w[h * HD * 25 + i];
        __syncthreads();

        // q = depthwise 5x5 conv (pad 2) on lh slice, + bias. layout [d][p]
        for (int idx = tid; idx < HD * NPOS; idx += 256) {
            int d = idx >> 6, p = idx & 63, iy = p >> 3, ix = p & 7;
            float acc = dw_b[h * HD + d];
            #pragma unroll
            for (int ky = 0; ky < 5; ++ky) {
                int yy = iy + ky - 2;
                if (yy < 0 || yy > 7) continue;
                #pragma unroll
                for (int kx = 0; kx < 5; ++kx) {
                    int xc = ix + kx - 2;
                    if (xc < 0 || xc > 7) continue;
                    acc += s_w[d * 25 + ky * 5 + kx] * s_lh[d * 64 + yy * 8 + xc];
                }
            }
            s_q[idx] = acc;
        }
        __syncthreads();

        // attn[n][m] = (q^T k) * scale + bias
        for (int idx = tid; idx < NPOS * NPOS; idx += 256) {
            int n = idx >> 6, m = idx & 63;
            float acc = 0.f;
            #pragma unroll
            for (int d = 0; d < HD; ++d) acc += s_q[d * 64 + n] * s_k[d * 64 + m];
            s_attn[n * 65 + m] = acc * ATT_SCALE + s_ab[h * 64 + bias_idx[idx]];
        }
        __syncthreads();

        // row softmax
        if (tid < NPOS) {
            float* row = s_attn + tid * 65;
            float mx = row[0];
            #pragma unroll 8
            for (int m = 1; m < 64; ++m) mx = fmaxf(mx, row[m]);
            float sum = 0.f;
            #pragma unroll 8
            for (int m = 0; m < 64; ++m) { float e = __expf(row[m] - mx); row[m] = e; sum += e; }
            float inv = 1.0f / sum;
            #pragma unroll 8
            for (int m = 0; m < 64; ++m) row[m] *= inv;
        }
        __syncthreads();

        // out[d][n] = sum_m v[d][m] * attn[n][m]
        float accs[8];
        #pragma unroll
        for (int r = 0; r < 8; ++r) {
            int idx = tid + r * 256;
            int d = idx >> 6, n = idx & 63;
            float acc = 0.f;
            #pragma unroll
            for (int m = 0; m < 64; ++m) acc += s_v[d * 64 + m] * s_attn[n * 65 + m];
            accs[r] = acc;
        }
        __syncthreads();
        int nbase = (win * CC + (h + 1) * HD) * NPOS;
        #pragma unroll
        for (int r = 0; r < 8; ++r) {
            int idx = tid + r * 256;
            int d = idx >> 6, n = idx & 63;
            s_out[(h * HD + d) * NPOS + n] = fmaxf(accs[r], 0.f);
            if (h < NHEADS - 1) s_v[d * 64 + n] = accs[r] + g_llw[nbase + d * 64 + n];
        }
        __syncthreads();
    }

    // proj: out[o][n] = proj_b[o] + sum_c W[o][c] * relu_out[c][n]
    {
        int o = tid;
        const float* Wrow = proj_w + o * CC;
        float pb = proj_b[o];
        float* outp = g_llout + (win * CC + o) * NPOS;
        for (int nb = 0; nb < NPOS; nb += 8) {
            float a[8];
            #pragma unroll
            for (int j = 0; j < 8; ++j) a[j] = pb;
            for (int c = 0; c < CC; ++c) {
                float w = Wrow[c];
                const float* so = s_out + c * NPOS + nb;
                #pragma unroll
                for (int j = 0; j < 8; ++j) a[j] += w * so[j];
            }
            #pragma unroll
            for (int j = 0; j < 8; ++j) outp[nb + j] = a[j];
        }
    }
}

// ---------------------------------------------------------------------------
// Kernel C: inverse wavelet. out[2y+r][2x+s] = sum_j iwt[4ch+j][r][s]*wtout_j
// ---------------------------------------------------------------------------
__global__ void iwt_kernel(const float* __restrict__ iwf, float* __restrict__ out) {
    int idx = blockIdx.x * blockDim.x + threadIdx.x;
    if (idx >= BB * CC * H2 * W2) return;
    int xx = idx & 127;
    int y  = (idx >> 7) & 127;
    int ch = (idx >> 14) & 255;
    int b  = idx >> 22;

    int win = b * 256 + (y >> 3) * 16 + (xx >> 3);
    int off = (win * CC + ch) * NPOS + (y & 7) * 8 + (xx & 7);
    float v0 = g_llout[off];
    float v1 = g_lhw[off];
    float v2 = g_hlw[off];
    float v3 = g_hhw[off];

    const float* w = iwf + ch * 16;  // iwt_filter[(4ch+j)][0][r][s]
    float* po = out + (((size_t)(b * CC + ch) * 256 + 2 * y) * 256 + 2 * xx);
    po[0]   = w[0] * v0 + w[4] * v1 + w[8]  * v2 + w[12] * v3;  // r=0,s=0
    po[1]   = w[1] * v0 + w[5] * v1 + w[9]  * v2 + w[13] * v3;  // r=0,s=1
    po[256] = w[2] * v0 + w[6] * v1 + w[10] * v2 + w[14] * v3;  // r=1,s=0
    po[257] = w[3] * v0 + w[7] * v1 + w[11] * v2 + w[15] * v3;  // r=1,s=1
}

// ---------------------------------------------------------------------------
extern "C" void kernel_launch(void* const* d_in, const int* in_sizes, int n_in,
                              void* d_out, int out_size) {
    const float* x    = (const float*)d_in[0];
    const float* wtf  = (const float*)d_in[1];
    const float* iwtf = (const float*)d_in[2];
    const float* dww  = (const float*)d_in[3];
    const float* dwb  = (const float*)d_in[4];
    const float* pw   = (const float*)d_in[5];
    const float* pb   = (const float*)d_in[6];
    const float* ab   = (const float*)d_in[7];
    const int*   bidx = (const int*)  d_in[8];
    float* out = (float*)d_out;

    int total = BB * CC * H2 * W2;  // 8,388,608
    wt_kernel<<<(total + 255) / 256, 256>>>(x, wtf);

    size_t smem = (size_t)(512 + 800 + 4 * 2048 + 64 * 65 + CC * NPOS) * sizeof(float);
    cudaFuncSetAttribute(attn_kernel, cudaFuncAttributeMaxDynamicSharedMemorySize, (int)smem);
    attn_kernel<<<NWIN, 256, smem>>>(dww, dwb, pw, pb, ab, bidx);

    iwt_kernel<<<(total + 255) / 256, 256>>>(iwtf, out);
}

// round 7
// speedup vs baseline: 3.4607x; 3.4607x over previous
#include <cuda_runtime.h>
#include <cuda_bf16.h>
#include <math.h>

#define BB 2
#define CC 256
#define H2 128
#define W2 128
#define NWIN 512      // BB * 16 * 16
#define NPOS 64
#define NHEADS 8
#define HD 32
#define ATT_SCALE 0.17677669529663687f  // 32^-0.5
#define APAD 68       // attn row stride (mult of 4, not mult of 32)

// Scratch in window layout: [win][ch][p], p = iy*8+ix
__device__ float g_llw  [NWIN * CC * NPOS];
__device__ float g_lhw  [NWIN * CC * NPOS];
__device__ float g_hlw  [NWIN * CC * NPOS];
__device__ float g_hhw  [NWIN * CC * NPOS];
__device__ float g_relu [NWIN * CC * NPOS];   // relu'd head outputs
__device__ float g_llout[NWIN * CC * NPOS];   // proj output

// ---------------------------------------------------------------------------
// Kernel A: forward wavelet (depthwise 2x2 stride-2), write window layout
// ---------------------------------------------------------------------------
__global__ void wt_kernel(const float* __restrict__ x, const float* __restrict__ wf) {
    int idx = blockIdx.x * blockDim.x + threadIdx.x;
    if (idx >= BB * CC * H2 * W2) return;
    int xx = idx & 127;
    int y  = (idx >> 7) & 127;
    int ch = (idx >> 14) & 255;
    int b  = idx >> 22;

    const float* px = x + (((size_t)(b * CC + ch) * 256 + 2 * y) * 256 + 2 * xx);
    float r00 = px[0], r01 = px[1], r10 = px[256], r11 = px[257];

    int win = b * 256 + (y >> 3) * 16 + (xx >> 3);
    int off = (win * CC + ch) * NPOS + (y & 7) * 8 + (xx & 7);
    const float* w = wf + ch * 16;

    g_llw[off] = w[0]  * r00 + w[1]  * r01 + w[2]  * r10 + w[3]  * r11;
    g_lhw[off] = w[4]  * r00 + w[5]  * r01 + w[6]  * r10 + w[7]  * r11;
    g_hlw[off] = w[8]  * r00 + w[9]  * r01 + w[10] * r10 + w[11] * r11;
    g_hhw[off] = w[12] * r00 + w[13] * r01 + w[14] * r10 + w[15] * r11;
}

// ---------------------------------------------------------------------------
// Kernel B: per-window cascaded head attention (+relu), NO proj.
// 256 threads per CTA, ~55 KB smem -> multiple CTAs/SM.
// ---------------------------------------------------------------------------
__global__ void attn_kernel(const float* __restrict__ dw_w,
                            const float* __restrict__ dw_b,
                            const float* __restrict__ ab) {
    extern __shared__ float sm[];
    float* s_ab   = sm;               // 512   (8 heads x 64 offsets)
    float* s_w    = s_ab + 512;       // 800   (32 ch x 25 taps)
    float* s_lh   = s_w + 800;        // 2048
    float* s_k    = s_lh + 2048;      // 2048
    float* s_v    = s_k + 2048;       // 2048
    float* s_q    = s_v + 2048;       // 2048  layout [d][p]
    float* s_attn = s_q + 2048;       // 64*APAD

    int win = blockIdx.x;
    int tid = threadIdx.x;

    for (int i = tid; i < 512; i += 256) s_ab[i] = ab[i];
    {   // head-0 v = llw[:, 0:32]
        int base = (win * CC) * NPOS;
        for (int i = tid; i < HD * NPOS; i += 256) s_v[i] = g_llw[base + i];
    }

    // QK micro-tile coords (4n x 4m per thread)
    const int tn = (tid >> 4) << 2;
    const int tm = (tid & 15) << 2;
    // bias index pieces for the 4x4 tile
    const int yn0 = tn >> 3;          // all 4 n in a group of 4 share (n>>3)? no:
    (void)yn0;

    for (int h = 0; h < NHEADS; ++h) {
        int base = (win * CC + h * HD) * NPOS;
        for (int i = tid; i < HD * NPOS; i += 256) {
            s_lh[i] = g_lhw[base + i];
            s_k[i]  = g_hlw[base + i];
        }
        for (int i = tid; i < HD * 25; i += 256) s_w[i] = dw_w[h * HD * 25 + i];
        __syncthreads();

        // q = depthwise 5x5 conv (pad 2) on lh slice, + bias. layout [d][p]
        for (int idx = tid; idx < HD * NPOS; idx += 256) {
            int d = idx >> 6, p = idx & 63, iy = p >> 3, ix = p & 7;
            float acc = dw_b[h * HD + d];
            #pragma unroll
            for (int ky = 0; ky < 5; ++ky) {
                int yy = iy + ky - 2;
                if (yy < 0 || yy > 7) continue;
                #pragma unroll
                for (int kx = 0; kx < 5; ++kx) {
                    int xc = ix + kx - 2;
                    if (xc < 0 || xc > 7) continue;
                    acc += s_w[d * 25 + ky * 5 + kx] * s_lh[d * 64 + yy * 8 + xc];
                }
            }
            s_q[idx] = acc;
        }
        __syncthreads();

        // attn[n][m] = (q^T k)*scale + bias ; 4x4 register tile per thread
        {
            float acc[4][4];
            #pragma unroll
            for (int i = 0; i < 4; ++i)
                #pragma unroll
                for (int j = 0; j < 4; ++j) acc[i][j] = 0.f;
            #pragma unroll 8
            for (int d = 0; d < HD; ++d) {
                float4 q4 = *(const float4*)&s_q[d * 64 + tn];
                float4 k4 = *(const float4*)&s_k[d * 64 + tm];
                float qq[4] = {q4.x, q4.y, q4.z, q4.w};
                float kk[4] = {k4.x, k4.y, k4.z, k4.w};
                #pragma unroll
                for (int i = 0; i < 4; ++i)
                    #pragma unroll
                    for (int j = 0; j < 4; ++j) acc[i][j] += qq[i] * kk[j];
            }
            #pragma unroll
            for (int i = 0; i < 4; ++i) {
                int n = tn + i, yn = n >> 3, xn = n & 7;
                #pragma unroll
                for (int j = 0; j < 4; ++j) {
                    int m = tm + j, ym = m >> 3, xm = m & 7;
                    int bi = abs(yn - ym) * 8 + abs(xn - xm);
                    s_attn[n * APAD + m] = acc[i][j] * ATT_SCALE + s_ab[h * 64 + bi];
                }
            }
        }
        __syncthreads();

        // row softmax: 4 threads per row (consecutive lanes -> shfl)
        {
            int row = tid >> 2, quad = tid & 3;
            float* rp = s_attn + row * APAD + quad * 16;
            float mx = rp[0];
            #pragma unroll
            for (int m = 1; m < 16; ++m) mx = fmaxf(mx, rp[m]);
            mx = fmaxf(mx, __shfl_xor_sync(0xffffffff, mx, 1));
            mx = fmaxf(mx, __shfl_xor_sync(0xffffffff, mx, 2));
            float sum = 0.f;
            float ev[16];
            #pragma unroll
            for (int m = 0; m < 16; ++m) { ev[m] = __expf(rp[m] - mx); sum += ev[m]; }
            sum += __shfl_xor_sync(0xffffffff, sum, 1);
            sum += __shfl_xor_sync(0xffffffff, sum, 2);
            float inv = 1.0f / sum;
            #pragma unroll
            for (int m = 0; m < 16; ++m) rp[m] = ev[m] * inv;
        }
        __syncthreads();

        // out[d][n] = sum_m v[d][m] * attn[n][m]  (float4 inner)
        float accs[8];
        #pragma unroll
        for (int r = 0; r < 8; ++r) {
            int idx = tid + r * 256;
            int d = idx >> 6, n = idx & 63;
            float acc = 0.f;
            #pragma unroll
            for (int m = 0; m < 64; m += 4) {
                float4 v4 = *(const float4*)&s_v[d * 64 + m];
                float4 a4 = *(const float4*)&s_attn[n * APAD + m];
                acc += v4.x * a4.x + v4.y * a4.y + v4.z * a4.z + v4.w * a4.w;
            }
            accs[r] = acc;
        }
        __syncthreads();
        int nbase = (win * CC + (h + 1) * HD) * NPOS;
        int obase = (win * CC + h * HD) * NPOS;
        #pragma unroll
        for (int r = 0; r < 8; ++r) {
            int idx = tid + r * 256;
            int d = idx >> 6, n = idx & 63;
            g_relu[obase + idx] = fmaxf(accs[r], 0.f);
            if (h < NHEADS - 1) s_v[d * 64 + n] = accs[r] + g_llw[nbase + idx];
        }
        __syncthreads();
    }
}

// ---------------------------------------------------------------------------
// Kernel B2: batched proj GEMM. One CTA per window:
//   out[o][n] = pb[o] + sum_c W[o][c] * relu[c][n]   (256x64 out, K=256)
// 256 threads, 8x8 register tiles, W staged transposed in smem.
// ---------------------------------------------------------------------------
__global__ void proj_kernel(const float* __restrict__ pw,
                            const float* __restrict__ pb) {
    __shared__ float sW[32 * 257];   // [c_local][o], pad-257 conflict-free
    __shared__ float sX[32 * 64];    // [c_local][n]

    int win = blockIdx.x;
    int tid = threadIdx.x;
    int to = (tid >> 3) << 3;        // 0..248 step 8
    int tn = (tid & 7) << 3;         // 0..56  step 8

    float acc[8][8];
    #pragma unroll
    for (int i = 0; i < 8; ++i)
        #pragma unroll
        for (int j = 0; j < 8; ++j) acc[i][j] = 0.f;

    for (int c0 = 0; c0 < CC; c0 += 32) {
        // stage W[:, c0:c0+32] transposed; each warp loads one o-row (32 c's)
        for (int i = tid; i < 256 * 32; i += 256) {
            int o = i >> 5, cl = i & 31;
            sW[cl * 257 + o] = pw[o * 256 + c0 + cl];
        }
        // stage relu chunk [32 c][64 n]
        for (int i = tid; i < 32 * 64; i += 256) {
            int c = i >> 6;
            sX[i] = g_relu[(win * CC + c0 + c) * NPOS + (i & 63)];
        }
        __syncthreads();

        #pragma unroll 4
        for (int cl = 0; cl < 32; ++cl) {
            float wreg[8];
            #pragma unroll
            for (int i = 0; i < 8; ++i) wreg[i] = sW[cl * 257 + to + i];
            float4 xlo = *(const float4*)&sX[cl * 64 + tn];
            float4 xhi = *(const float4*)&sX[cl * 64 + tn + 4];
            float xr[8] = {xlo.x, xlo.y, xlo.z, xlo.w, xhi.x, xhi.y, xhi.z, xhi.w};
            #pragma unroll
            for (int i = 0; i < 8; ++i)
                #pragma unroll
                for (int j = 0; j < 8; ++j) acc[i][j] += wreg[i] * xr[j];
        }
        __syncthreads();
    }

    #pragma unroll
    for (int i = 0; i < 8; ++i) {
        float b = pb[to + i];
        float* outp = g_llout + (win * CC + to + i) * NPOS + tn;
        #pragma unroll
        for (int j = 0; j < 8; ++j) outp[j] = acc[i][j] + b;
    }
}

// ---------------------------------------------------------------------------
// Kernel C: inverse wavelet. out[2y+r][2x+s] = sum_j iwt[4ch+j][r][s]*wtout_j
// ---------------------------------------------------------------------------
__global__ void iwt_kernel(const float* __restrict__ iwf, float* __restrict__ out) {
    int idx = blockIdx.x * blockDim.x + threadIdx.x;
    if (idx >= BB * CC * H2 * W2) return;
    int xx = idx & 127;
    int y  = (idx >> 7) & 127;
    int ch = (idx >> 14) & 255;
    int b  = idx >> 22;

    int win = b * 256 + (y >> 3) * 16 + (xx >> 3);
    int off = (win * CC + ch) * NPOS + (y & 7) * 8 + (xx & 7);
    float v0 = g_llout[off];
    float v1 = g_lhw[off];
    float v2 = g_hlw[off];
    float v3 = g_hhw[off];

    const float* w = iwf + ch * 16;
    float* po = out + (((size_t)(b * CC + ch) * 256 + 2 * y) * 256 + 2 * xx);
    po[0]   = w[0] * v0 + w[4] * v1 + w[8]  * v2 + w[12] * v3;
    po[1]   = w[1] * v0 + w[5] * v1 + w[9]  * v2 + w[13] * v3;
    po[256] = w[2] * v0 + w[6] * v1 + w[10] * v2 + w[14] * v3;
    po[257] = w[3] * v0 + w[7] * v1 + w[11] * v2 + w[15] * v3;
}

// ---------------------------------------------------------------------------
extern "C" void kernel_launch(void* const* d_in, const int* in_sizes, int n_in,
                              void* d_out, int out_size) {
    const float* x    = (const float*)d_in[0];
    const float* wtf  = (const float*)d_in[1];
    const float* iwtf = (const float*)d_in[2];
    const float* dww  = (const float*)d_in[3];
    const float* dwb  = (const float*)d_in[4];
    const float* pw   = (const float*)d_in[5];
    const float* pb   = (const float*)d_in[6];
    const float* ab   = (const float*)d_in[7];
    float* out = (float*)d_out;

    int total = BB * CC * H2 * W2;  // 8,388,608
    wt_kernel<<<(total + 255) / 256, 256>>>(x, wtf);

    size_t smem = (size_t)(512 + 800 + 4 * 2048 + 64 * APAD) * sizeof(float);
    cudaFuncSetAttribute(attn_kernel, cudaFuncAttributeMaxDynamicSharedMemorySize, (int)smem);
    attn_kernel<<<NWIN, 256, smem>>>(dww, dwb, ab);

    proj_kernel<<<NWIN, 256>>>(pw, pb);

    iwt_kernel<<<(total + 255) / 256, 256>>>(iwtf, out);
}

// round 8
// speedup vs baseline: 4.1171x; 1.1897x over previous
#include <cuda_runtime.h>
#include <cuda_bf16.h>
#include <math.h>

#define BB 2
#define CC 256
#define H2 128
#define W2 128
#define NWIN 512
#define NPOS 64
#define NHEADS 8
#define HD 32
#define ATT_SCALE 0.17677669529663687f
#define APAD 68   // attn row stride in floats (16B aligned rows)

// ---------------- packed f32x2 helpers ----------------
typedef unsigned long long ull;

__device__ __forceinline__ ull pack2(float lo, float hi) {
    ull r; asm("mov.b64 %0, {%1,%2};" : "=l"(r) : "f"(lo), "f"(hi)); return r;
}
__device__ __forceinline__ void fma2(ull& d, ull a, ull b) {
    asm("fma.rn.f32x2 %0, %1, %2, %0;" : "+l"(d) : "l"(a), "l"(b));
}
__device__ __forceinline__ float2 unpack2(ull v) {
    float2 f; asm("mov.b64 {%0,%1}, %2;" : "=f"(f.x), "=f"(f.y) : "l"(v)); return f;
}

// Scratch in window layout: [win][ch][p], p = iy*8+ix
__device__ float g_llw  [NWIN * CC * NPOS];
__device__ float g_lhw  [NWIN * CC * NPOS];
__device__ float g_hlw  [NWIN * CC * NPOS];
__device__ float g_hhw  [NWIN * CC * NPOS];
__device__ float g_relu [NWIN * CC * NPOS];
__device__ float g_llout[NWIN * CC * NPOS];

// ---------------------------------------------------------------------------
// Kernel A: forward wavelet (depthwise 2x2 stride-2), 2 pixels per thread
// ---------------------------------------------------------------------------
__global__ void wt_kernel(const float* __restrict__ x, const float* __restrict__ wf) {
    int idx = blockIdx.x * blockDim.x + threadIdx.x;   // total/2 threads
    int xp = idx & 63;                // xx/2
    int y  = (idx >> 6) & 127;
    int ch = (idx >> 13) & 255;
    int b  = idx >> 21;
    int xx = xp << 1;

    const float* px = x + (((size_t)(b * CC + ch) * 256 + 2 * y) * 256 + 2 * xx);
    float4 r0 = *(const float4*)px;          // row 2y  : pixels A,B
    float4 r1 = *(const float4*)(px + 256);  // row 2y+1

    int win = b * 256 + (y >> 3) * 16 + (xx >> 3);
    int off = (win * CC + ch) * NPOS + (y & 7) * 8 + (xx & 7);
    const float* w = wf + ch * 16;

    // pixel A: r0.x r0.y / r1.x r1.y ; pixel B: r0.z r0.w / r1.z r1.w
    float2 ll, lh, hl, hh;
    ll.x = w[0]*r0.x + w[1]*r0.y + w[2]*r1.x + w[3]*r1.y;
    ll.y = w[0]*r0.z + w[1]*r0.w + w[2]*r1.z + w[3]*r1.w;
    lh.x = w[4]*r0.x + w[5]*r0.y + w[6]*r1.x + w[7]*r1.y;
    lh.y = w[4]*r0.z + w[5]*r0.w + w[6]*r1.z + w[7]*r1.w;
    hl.x = w[8]*r0.x + w[9]*r0.y + w[10]*r1.x + w[11]*r1.y;
    hl.y = w[8]*r0.z + w[9]*r0.w + w[10]*r1.z + w[11]*r1.w;
    hh.x = w[12]*r0.x + w[13]*r0.y + w[14]*r1.x + w[15]*r1.y;
    hh.y = w[12]*r0.z + w[13]*r0.w + w[14]*r1.z + w[15]*r1.w;

    *(float2*)&g_llw[off] = ll;
    *(float2*)&g_lhw[off] = lh;
    *(float2*)&g_hlw[off] = hl;
    *(float2*)&g_hhw[off] = hh;
}

// ---------------------------------------------------------------------------
// Kernel B: per-window cascaded head attention (+relu)
// ---------------------------------------------------------------------------
__global__ void __launch_bounds__(256) attn_kernel(const float* __restrict__ dw_w,
                                                   const float* __restrict__ dw_b,
                                                   const float* __restrict__ ab) {
    extern __shared__ float sm[];
    float* s_ab   = sm;               // 512
    float* s_w    = s_ab + 512;       // 800
    float* s_lh   = s_w + 800;        // 2048
    float* s_k    = s_lh + 2048;      // 2048
    float* s_v    = s_k + 2048;       // 2048
    float* s_q    = s_v + 2048;       // 2048  [d][p]
    float* s_attn = s_q + 2048;       // 64*APAD

    int win = blockIdx.x;
    int tid = threadIdx.x;

    for (int i = tid; i < 512; i += 256) s_ab[i] = ab[i];
    {   // head-0 v = llw[:, 0:32]
        const float4* src = (const float4*)(g_llw + (size_t)(win * CC) * NPOS);
        float4* dst = (float4*)s_v;
        for (int i = tid; i < HD * NPOS / 4; i += 256) dst[i] = src[i];
    }

    const int cd = tid >> 3;          // conv: d (0..31)
    const int cix = tid & 7;          // conv: ix
    const int tn = (tid >> 4) << 2;   // QK 4x4 tile
    const int tm = (tid & 15) << 2;
    const int ad0 = (tid >> 4) << 2;  // AV 4x4 tile (tid<128): d group 0..7
    const int an0 = (tid & 15) << 2;  //                        n group 0..15

    for (int h = 0; h < NHEADS; ++h) {
        {   // stage lh, k (hl) via float4
            const float4* slh = (const float4*)(g_lhw + (size_t)(win * CC + h * HD) * NPOS);
            const float4* shl = (const float4*)(g_hlw + (size_t)(win * CC + h * HD) * NPOS);
            float4* dlh = (float4*)s_lh;
            float4* dk  = (float4*)s_k;
            for (int i = tid; i < HD * NPOS / 4; i += 256) { dlh[i] = slh[i]; dk[i] = shl[i]; }
            for (int i = tid; i < HD * 25; i += 256) s_w[i] = dw_w[h * HD * 25 + i];
        }
        __syncthreads();

        // ---- q = depthwise 5x5 conv (pad 2) + bias; thread = (d, ix) ----
        {
            float wv[25];
            #pragma unroll
            for (int t = 0; t < 25; ++t) wv[t] = s_w[cd * 25 + t];
            float colv[5][8];
            #pragma unroll
            for (int kx = 0; kx < 5; ++kx) {
                int xc = cix + kx - 2;
                bool ok = (xc >= 0) && (xc < 8);
                #pragma unroll
                for (int iy = 0; iy < 8; ++iy)
                    colv[kx][iy] = ok ? s_lh[cd * 64 + iy * 8 + xc] : 0.f;
            }
            float bias = dw_b[h * HD + cd];
            #pragma unroll
            for (int iy = 0; iy < 8; ++iy) {
                float acc = bias;
                #pragma unroll
                for (int ky = 0; ky < 5; ++ky) {
                    int yy = iy + ky - 2;
                    if (yy < 0 || yy > 7) continue;
                    #pragma unroll
                    for (int kx = 0; kx < 5; ++kx)
                        acc += wv[ky * 5 + kx] * colv[kx][yy];
                }
                s_q[cd * 64 + iy * 8 + cix] = acc;
            }
        }
        __syncthreads();

        // ---- QK: attn[n][m] = (q^T k)*scale + bias ; 4x4 tile, f32x2 ----
        {
            ull acc2[4][2] = {};
            #pragma unroll 8
            for (int d = 0; d < HD; ++d) {
                float4 q4 = *(const float4*)&s_q[d * 64 + tn];
                ulonglong2 k2 = *(const ulonglong2*)&s_k[d * 64 + tm];
                ull qp[4] = {pack2(q4.x, q4.x), pack2(q4.y, q4.y),
                             pack2(q4.z, q4.z), pack2(q4.w, q4.w)};
                #pragma unroll
                for (int i = 0; i < 4; ++i) {
                    fma2(acc2[i][0], qp[i], k2.x);
                    fma2(acc2[i][1], qp[i], k2.y);
                }
            }
            #pragma unroll
            for (int i = 0; i < 4; ++i) {
                int n = tn + i, yn = n >> 3, xn = n & 7;
                #pragma unroll
                for (int jp = 0; jp < 2; ++jp) {
                    float2 p = unpack2(acc2[i][jp]);
                    int m0 = tm + 2 * jp;
                    int b0 = abs(yn - (m0 >> 3)) * 8 + abs(xn - (m0 & 7));
                    int m1 = m0 + 1;
                    int b1 = abs(yn - (m1 >> 3)) * 8 + abs(xn - (m1 & 7));
                    s_attn[n * APAD + m0] = p.x * ATT_SCALE + s_ab[h * 64 + b0];
                    s_attn[n * APAD + m1] = p.y * ATT_SCALE + s_ab[h * 64 + b1];
                }
            }
        }
        __syncthreads();

        // ---- row softmax: 4 threads per row ----
        {
            int row = tid >> 2, quad = tid & 3;
            float* rp = s_attn + row * APAD + quad * 16;
            float mx = rp[0];
            #pragma unroll
            for (int m = 1; m < 16; ++m) mx = fmaxf(mx, rp[m]);
            mx = fmaxf(mx, __shfl_xor_sync(0xffffffff, mx, 1));
            mx = fmaxf(mx, __shfl_xor_sync(0xffffffff, mx, 2));
            float sum = 0.f, ev[16];
            #pragma unroll
            for (int m = 0; m < 16; ++m) { ev[m] = __expf(rp[m] - mx); sum += ev[m]; }
            sum += __shfl_xor_sync(0xffffffff, sum, 1);
            sum += __shfl_xor_sync(0xffffffff, sum, 2);
            float inv = 1.0f / sum;
            #pragma unroll
            for (int m = 0; m < 16; ++m) rp[m] = ev[m] * inv;
        }
        __syncthreads();

        // ---- AV: out[d][n] = sum_m v[d][m]*attn[n][m]; 4x4 tile, 128 thr ----
        ull acc2[4][4];
        if (tid < 128) {
            #pragma unroll
            for (int i = 0; i < 4; ++i)
                #pragma unroll
                for (int j = 0; j < 4; ++j) acc2[i][j] = 0ULL;
            #pragma unroll 4
            for (int mq = 0; mq < 16; ++mq) {
                ulonglong2 vv[4], aa[4];
                #pragma unroll
                for (int i = 0; i < 4; ++i)
                    vv[i] = *(const ulonglong2*)&s_v[(ad0 + i) * 64 + mq * 4];
                #pragma unroll
                for (int j = 0; j < 4; ++j)
                    aa[j] = *(const ulonglong2*)&s_attn[(an0 + j) * APAD + mq * 4];
                #pragma unroll
                for (int i = 0; i < 4; ++i)
                    #pragma unroll
                    for (int j = 0; j < 4; ++j) {
                        fma2(acc2[i][j], vv[i].x, aa[j].x);
                        fma2(acc2[i][j], vv[i].y, aa[j].y);
                    }
            }
        }
        __syncthreads();
        if (tid < 128) {
            size_t obase = (size_t)(win * CC + h * HD) * NPOS;
            size_t nbase = (size_t)(win * CC + (h + 1) * HD) * NPOS;
            #pragma unroll
            for (int i = 0; i < 4; ++i) {
                int d = ad0 + i;
                float val[4];
                #pragma unroll
                for (int j = 0; j < 4; ++j) {
                    float2 p = unpack2(acc2[i][j]);
                    val[j] = p.x + p.y;
                }
                float4 ro = make_float4(fmaxf(val[0], 0.f), fmaxf(val[1], 0.f),
                                        fmaxf(val[2], 0.f), fmaxf(val[3], 0.f));
                *(float4*)&g_relu[obase + d * 64 + an0] = ro;
                if (h < NHEADS - 1) {
                    float4 l4 = *(const float4*)&g_llw[nbase + d * 64 + an0];
                    *(float4*)&s_v[d * 64 + an0] =
                        make_float4(val[0] + l4.x, val[1] + l4.y,
                                    val[2] + l4.z, val[3] + l4.w);
                }
            }
        }
        __syncthreads();
    }
}

// ---------------------------------------------------------------------------
// Kernel B2: batched proj GEMM, f32x2 inner, 8x8 tile
// ---------------------------------------------------------------------------
__global__ void __launch_bounds__(256) proj_kernel(const float* __restrict__ pw,
                                                   const float* __restrict__ pb) {
    __shared__ float sW[32 * 257];   // [c_local][o], conflict-free stride
    __shared__ float sX[32 * 64];    // [c_local][n]

    int win = blockIdx.x;
    int tid = threadIdx.x;
    int to = (tid >> 3) << 3;
    int tn = (tid & 7) << 3;

    ull acc2[8][4];
    #pragma unroll
    for (int i = 0; i < 8; ++i)
        #pragma unroll
        for (int j = 0; j < 4; ++j) acc2[i][j] = 0ULL;

    for (int c0 = 0; c0 < CC; c0 += 32) {
        for (int i = tid; i < 256 * 32; i += 256) {
            int o = i >> 5, cl = i & 31;
            sW[cl * 257 + o] = pw[o * 256 + c0 + cl];
        }
        {
            const float4* src = (const float4*)(g_relu + (size_t)(win * CC + c0) * NPOS);
            float4* dst = (float4*)sX;
            for (int i = tid; i < 32 * 64 / 4; i += 256) dst[i] = src[i];
        }
        __syncthreads();

        #pragma unroll 4
        for (int cl = 0; cl < 32; ++cl) {
            ull wp[8];
            #pragma unroll
            for (int i = 0; i < 8; ++i) {
                float w = sW[cl * 257 + to + i];
                wp[i] = pack2(w, w);
            }
            ulonglong2 x0 = *(const ulonglong2*)&sX[cl * 64 + tn];
            ulonglong2 x1 = *(const ulonglong2*)&sX[cl * 64 + tn + 4];
            ull xp[4] = {x0.x, x0.y, x1.x, x1.y};
            #pragma unroll
            for (int i = 0; i < 8; ++i)
                #pragma unroll
                for (int j = 0; j < 4; ++j) fma2(acc2[i][j], wp[i], xp[j]);
        }
        __syncthreads();
    }

    #pragma unroll
    for (int i = 0; i < 8; ++i) {
        float b = pb[to + i];
        float* outp = g_llout + (size_t)(win * CC + to + i) * NPOS + tn;
        float2 p0 = unpack2(acc2[i][0]);
        float2 p1 = unpack2(acc2[i][1]);
        float2 p2 = unpack2(acc2[i][2]);
        float2 p3 = unpack2(acc2[i][3]);
        *(float4*)outp       = make_float4(p0.x + b, p0.y + b, p1.x + b, p1.y + b);
        *(float4*)(outp + 4) = make_float4(p2.x + b, p2.y + b, p3.x + b, p3.y + b);
    }
}

// ---------------------------------------------------------------------------
// Kernel C: inverse wavelet, 2 cells per thread
// ---------------------------------------------------------------------------
__global__ void iwt_kernel(const float* __restrict__ iwf, float* __restrict__ out) {
    int idx = blockIdx.x * blockDim.x + threadIdx.x;   // total/2 threads
    int xp = idx & 63;
    int y  = (idx >> 6) & 127;
    int ch = (idx >> 13) & 255;
    int b  = idx >> 21;
    int xx = xp << 1;

    int win = b * 256 + (y >> 3) * 16 + (xx >> 3);
    int off = (win * CC + ch) * NPOS + (y & 7) * 8 + (xx & 7);
    float2 v0 = *(const float2*)&g_llout[off];
    float2 v1 = *(const float2*)&g_lhw[off];
    float2 v2 = *(const float2*)&g_hlw[off];
    float2 v3 = *(const float2*)&g_hhw[off];

    const float* w = iwf + ch * 16;
    float* po = out + (((size_t)(b * CC + ch) * 256 + 2 * y) * 256 + 2 * xx);

    float4 r0, r1;
    r0.x = w[0]*v0.x + w[4]*v1.x + w[8]*v2.x  + w[12]*v3.x;
    r0.y = w[1]*v0.x + w[5]*v1.x + w[9]*v2.x  + w[13]*v3.x;
    r0.z = w[0]*v0.y + w[4]*v1.y + w[8]*v2.y  + w[12]*v3.y;
    r0.w = w[1]*v0.y + w[5]*v1.y + w[9]*v2.y  + w[13]*v3.y;
    r1.x = w[2]*v0.x + w[6]*v1.x + w[10]*v2.x + w[14]*v3.x;
    r1.y = w[3]*v0.x + w[7]*v1.x + w[11]*v2.x + w[15]*v3.x;
    r1.z = w[2]*v0.y + w[6]*v1.y + w[10]*v2.y + w[14]*v3.y;
    r1.w = w[3]*v0.y + w[7]*v1.y + w[11]*v2.y + w[15]*v3.y;

    *(float4*)po         = r0;
    *(float4*)(po + 256) = r1;
}

// ---------------------------------------------------------------------------
extern "C" void kernel_launch(void* const* d_in, const int* in_sizes, int n_in,
                              void* d_out, int out_size) {
    const float* x    = (const float*)d_in[0];
    const float* wtf  = (const float*)d_in[1];
    const float* iwtf = (const float*)d_in[2];
    const float* dww  = (const float*)d_in[3];
    const float* dwb  = (const float*)d_in[4];
    const float* pw   = (const float*)d_in[5];
    const float* pb   = (const float*)d_in[6];
    const float* ab   = (const float*)d_in[7];
    float* out = (float*)d_out;

    int half = BB * CC * H2 * W2 / 2;  // 4,194,304
    wt_kernel<<<half / 256, 256>>>(x, wtf);

    size_t smem = (size_t)(512 + 800 + 4 * 2048 + 64 * APAD) * sizeof(float);
    cudaFuncSetAttribute(attn_kernel, cudaFuncAttributeMaxDynamicSharedMemorySize, (int)smem);
    attn_kernel<<<NWIN, 256, smem>>>(dww, dwb, ab);

    proj_kernel<<<NWIN, 256>>>(pw, pb);

    iwt_kernel<<<half / 256, 256>>>(iwtf, out);
}